// round 1
// baseline (speedup 1.0000x reference)
#include <cuda_runtime.h>
#include <math.h>

#define NINS   2048
#define TOK    16
#define EMB    512
#define HID    256
#define G4     (4*HID)      // 1024
#define PAR    8
#define LEVELS 16
#define KROWS  (NINS/LEVELS) // 128

// ---------------- scratch (static device globals; no allocation) ----------------
__device__ float g_Xp[NINS*TOK*G4];      // 128 MiB: token input projections
__device__ float g_H[NINS*HID];          // token-LSTM hidden
__device__ float g_C[NINS*HID];          // token-LSTM cell
__device__ float g_gates[NINS*G4];       // gate scratch (token steps reuse; levels use first 128 rows)
__device__ float g_Gx[NINS*G4];          // instruction-LSTM input projections
__device__ float g_Hi[NINS*HID];         // instruction-LSTM hidden
__device__ float g_Ci[NINS*HID];         // instruction-LSTM cell
__device__ float g_h0[KROWS*HID];        // per-level gathered parent h
__device__ float g_c0[KROWS*HID];        // per-level gathered parent c
__device__ unsigned char g_pval[NINS*PAR];
__device__ int   g_appears[NINS];
__device__ float g_partial[64*HID];

// ---------------- prep: detect parent_valid dtype, normalize, compute 'appears' ----------------
__global__ void prep_kernel(const unsigned char* __restrict__ pv_raw,
                            const int* __restrict__ pidx)
{
    __shared__ int s_hi, s_b0;
    __shared__ int s_app[NINS];
    int tid = threadIdx.x;

    // Sample int32-element indices 256..4095. Under any layout these byte reads are
    // within the first 16384 bytes (smallest possible buffer: 1 byte/elem * 16384).
    int hi = 0, b0 = 0;
    for (int i = 256 + tid; i < 4096; i += 256) {
        hi |= pv_raw[4*i+1] | pv_raw[4*i+2] | pv_raw[4*i+3];
        b0 |= pv_raw[4*i+0];
    }
    if (tid == 0) { s_hi = 0; s_b0 = 0; }
    __syncthreads();
    if (hi) atomicOr(&s_hi, 1);
    if (b0) atomicOr(&s_b0, 1);
    __syncthreads();
    // s_hi==0  -> int32 (0/1, high bytes always zero)
    // s_hi!=0 && s_b0==0 -> float32 (1.0f = 00 00 80 3F, byte0 always zero)
    // else -> 1-byte bool
    int mode = (s_hi == 0) ? 0 : (s_b0 == 0 ? 1 : 2);

    for (int i = tid; i < NINS*PAR; i += 256) {
        unsigned char v;
        if (mode == 0)      v = (((const int*)pv_raw)[i]   != 0);
        else if (mode == 1) v = (((const float*)pv_raw)[i] != 0.0f);
        else                v = (pv_raw[i] != 0);
        g_pval[i] = v;
    }
    for (int i = tid; i < NINS; i += 256) s_app[i] = 0;
    __syncthreads();
    for (int i = tid; i < NINS*PAR; i += 256) {
        if (g_pval[i]) atomicAdd(&s_app[pidx[i]], 1);
    }
    __syncthreads();
    for (int i = tid; i < NINS; i += 256) g_appears[i] = s_app[i];
}

// ---------------- zero token-LSTM state ----------------
__global__ void zero_state_kernel()
{
    int idx = blockIdx.x * blockDim.x + threadIdx.x;
    if (idx < NINS*HID) { g_H[idx] = 0.0f; g_C[idx] = 0.0f; }
}

// ---------------- generic fp32 GEMM: C[M,N] = A[M,K] @ B[N,K]^T (+bias)(+Add) ----------------
// A row-major lda=K, B row-major ldb=K, C row-major ldc=N.
#define BM 64
#define BN 64
#define BKT 16
__global__ __launch_bounds__(256) void gemm_kernel(
    const float* __restrict__ A, const float* __restrict__ B,
    float* __restrict__ Cout,
    const float* __restrict__ Add, int addStride,
    const float* __restrict__ b1, const float* __restrict__ b2,
    int M, int Ncols, int Kdim)
{
    __shared__ float As[BKT][BM+1];
    __shared__ float Bs[BKT][BN+1];
    int bm = blockIdx.y * BM;
    int bn = blockIdx.x * BN;
    int tid = threadIdx.x;
    int tx = tid & 15, ty = tid >> 4;

    float acc[4][4];
#pragma unroll
    for (int i = 0; i < 4; i++)
#pragma unroll
        for (int j = 0; j < 4; j++) acc[i][j] = 0.0f;

    for (int k0 = 0; k0 < Kdim; k0 += BKT) {
#pragma unroll
        for (int u = 0; u < 4; u++) {
            int idx = u * 256 + tid;
            int r = idx >> 4;        // 0..63
            int k = idx & 15;        // 0..15
            As[k][r] = A[(size_t)(bm + r) * Kdim + k0 + k];
            Bs[k][r] = B[(size_t)(bn + r) * Kdim + k0 + k];
        }
        __syncthreads();
#pragma unroll
        for (int kk = 0; kk < BKT; kk++) {
            float a[4], b[4];
#pragma unroll
            for (int i = 0; i < 4; i++) a[i] = As[kk][ty*4+i];
#pragma unroll
            for (int j = 0; j < 4; j++) b[j] = Bs[kk][tx*4+j];
#pragma unroll
            for (int i = 0; i < 4; i++)
#pragma unroll
                for (int j = 0; j < 4; j++) acc[i][j] += a[i] * b[j];
        }
        __syncthreads();
    }

#pragma unroll
    for (int i = 0; i < 4; i++) {
        int m = bm + ty*4 + i;
#pragma unroll
        for (int j = 0; j < 4; j++) {
            int n = bn + tx*4 + j;
            float v = acc[i][j];
            if (b1)  v += b1[n] + b2[n];
            if (Add) v += Add[(size_t)m * addStride + n];
            Cout[(size_t)m * Ncols + n] = v;
        }
    }
}

// ---------------- LSTM gate update ----------------
__global__ void lstm_update_kernel(const float* __restrict__ gates,
                                   const float* __restrict__ cin,
                                   float* __restrict__ hout,
                                   float* __restrict__ cout,
                                   int total)
{
    int idx = blockIdx.x * blockDim.x + threadIdx.x;
    if (idx >= total) return;
    int n = idx >> 8;          // row
    int h = idx & 255;         // hidden unit
    const float* g = gates + (size_t)n * G4;
    float gi = g[h], gf = g[HID + h], gg = g[2*HID + h], go = g[3*HID + h];
    float c  = cin[idx];
    float si = 1.0f / (1.0f + expf(-gi));
    float sf = 1.0f / (1.0f + expf(-gf));
    float so = 1.0f / (1.0f + expf(-go));
    float cn = sf * c + si * tanhf(gg);
    float hn = so * tanhf(cn);
    cout[idx] = cn;
    hout[idx] = hn;
}

// ---------------- per-level parent gather (max combine) ----------------
__global__ void gather_kernel(const int* __restrict__ pidx, int l)
{
    int r   = blockIdx.x;            // 0..127
    int row = l * KROWS + r;
    int h   = threadIdx.x;           // 0..255
    __shared__ int sp[PAR];
    __shared__ int sv[PAR];
    if (h < PAR) {
        sp[h] = pidx[row*PAR + h];
        sv[h] = g_pval[row*PAR + h];
    }
    __syncthreads();
    float mh = -1e30f, mc = -1e30f;
    int has = 0;
#pragma unroll
    for (int p = 0; p < PAR; p++) {
        if (sv[p]) {
            has = 1;
            mh = fmaxf(mh, g_Hi[(size_t)sp[p]*HID + h]);
            mc = fmaxf(mc, g_Ci[(size_t)sp[p]*HID + h]);
        }
    }
    g_h0[r*HID + h] = has ? mh : 0.0f;
    g_c0[r*HID + h] = has ? mc : 0.0f;
}

// ---------------- final: masked max over roots, then dot with Wlin ----------------
__global__ void final1_kernel()
{
    int b = blockIdx.x;              // 64 blocks, 32 rows each
    int h = threadIdx.x;
    float m = -1e30f;
    for (int r = b*32; r < b*32 + 32; r++)
        if (g_appears[r] == 0) m = fmaxf(m, g_Hi[(size_t)r*HID + h]);
    g_partial[b*HID + h] = m;
}

__global__ void final2_kernel(const float* __restrict__ Wlin,
                              const float* __restrict__ blin,
                              float* __restrict__ out)
{
    int h = threadIdx.x;
    float m = -1e30f;
    for (int b = 0; b < 64; b++) m = fmaxf(m, g_partial[b*HID + h]);
    float v = m * Wlin[h];
    __shared__ float s[256];
    s[h] = v;
    __syncthreads();
    for (int st = 128; st > 0; st >>= 1) {
        if (h < st) s[h] += s[h + st];
        __syncthreads();
    }
    if (h == 0) out[0] = s[0] + blin[0];
}

// ---------------- launch ----------------
extern "C" void kernel_launch(void* const* d_in, const int* in_sizes, int n_in,
                              void* d_out, int out_size)
{
    const float* tokens   = (const float*)d_in[0];
    const int*   pidx     = (const int*)  d_in[1];
    const unsigned char* pval = (const unsigned char*)d_in[2];
    const float* Wih_tok  = (const float*)d_in[3];
    const float* Whh_tok  = (const float*)d_in[4];
    const float* bih_tok  = (const float*)d_in[5];
    const float* bhh_tok  = (const float*)d_in[6];
    const float* Wih_ins  = (const float*)d_in[7];
    const float* Whh_ins  = (const float*)d_in[8];
    const float* bih_ins  = (const float*)d_in[9];
    const float* bhh_ins  = (const float*)d_in[10];
    const float* Wlin     = (const float*)d_in[11];
    const float* blin     = (const float*)d_in[12];
    float* out = (float*)d_out;

    float *pXp, *pH, *pC, *pGates, *pGx, *pHi, *pCi, *ph0, *pc0;
    cudaGetSymbolAddress((void**)&pXp,    g_Xp);
    cudaGetSymbolAddress((void**)&pH,     g_H);
    cudaGetSymbolAddress((void**)&pC,     g_C);
    cudaGetSymbolAddress((void**)&pGates, g_gates);
    cudaGetSymbolAddress((void**)&pGx,    g_Gx);
    cudaGetSymbolAddress((void**)&pHi,    g_Hi);
    cudaGetSymbolAddress((void**)&pCi,    g_Ci);
    cudaGetSymbolAddress((void**)&ph0,    g_h0);
    cudaGetSymbolAddress((void**)&pc0,    g_c0);

    // prep: parent_valid normalization + appears
    prep_kernel<<<1, 256>>>(pval, pidx);
    // zero token-LSTM state
    zero_state_kernel<<<(NINS*HID + 255)/256, 256>>>();

    // Phase 1: Xp = tokens @ Wih_tok^T + (bih+bhh)   [32768 x 1024, K=512]
    gemm_kernel<<<dim3(G4/BN, (NINS*TOK)/BM), 256>>>(
        tokens, Wih_tok, pXp, nullptr, 0, bih_tok, bhh_tok,
        NINS*TOK, G4, EMB);

    // Phase 2: token-LSTM recurrence (16 steps)
    for (int t = 0; t < TOK; t++) {
        gemm_kernel<<<dim3(G4/BN, NINS/BM), 256>>>(
            pH, Whh_tok, pGates, pXp + (size_t)t * G4, TOK*G4,
            nullptr, nullptr, NINS, G4, HID);
        lstm_update_kernel<<<(NINS*HID + 255)/256, 256>>>(
            pGates, pC, pH, pC, NINS*HID);
    }

    // Phase 3a: Gx = ins_embed @ Wih_ins^T + (bih+bhh)
    gemm_kernel<<<dim3(G4/BN, NINS/BM), 256>>>(
        pH, Wih_ins, pGx, nullptr, 0, bih_ins, bhh_ins,
        NINS, G4, HID);

    // Phase 3b: DAG levels
    for (int l = 0; l < LEVELS; l++) {
        gather_kernel<<<KROWS, HID>>>(pidx, l);
        gemm_kernel<<<dim3(G4/BN, KROWS/BM), 256>>>(
            ph0, Whh_ins, pGates, pGx + (size_t)l * KROWS * G4, G4,
            nullptr, nullptr, KROWS, G4, HID);
        lstm_update_kernel<<<(KROWS*HID + 255)/256, 256>>>(
            pGates, pc0, pHi + (size_t)l * KROWS * HID, pCi + (size_t)l * KROWS * HID,
            KROWS*HID);
    }

    // Phase 4: roots -> masked max -> linear
    final1_kernel<<<64, 256>>>();
    final2_kernel<<<1, 256>>>(Wlin, blin, out);
}

// round 3
// speedup vs baseline: 2.0283x; 2.0283x over previous
#include <cuda_runtime.h>
#include <math.h>
#include <stdint.h>

#define NINS   2048
#define TOK    16
#define EMB    512
#define HID    256
#define G4     (4*HID)      // 1024
#define PAR    8
#define LEVELS 16
#define KROWS  (NINS/LEVELS) // 128

// ---------------- scratch (static device globals; no allocation) ----------------
__device__ float g_Xp[NINS*TOK*G4];      // 128 MiB: token input projections (unpermuted cols)
__device__ float g_H[NINS*HID];          // token-LSTM hidden (ping)
__device__ float g_C[NINS*HID];
__device__ float g_H2[NINS*HID];         // pong
__device__ float g_C2[NINS*HID];
__device__ float g_Gx[NINS*G4];          // instruction input projections (unpermuted cols)
__device__ float g_Hi[NINS*HID];
__device__ float g_Ci[NINS*HID];
__device__ float g_h0[KROWS*HID];
__device__ float g_c0[KROWS*HID];
__device__ float g_WhhTokP[G4*HID];      // gate-interleaved permuted Whh_tok
__device__ float g_WhhInsP[G4*HID];
__device__ unsigned char g_pval[NINS*PAR];
__device__ int   g_appears[NINS];
__device__ float g_partial[64*HID];

// ---------------- prep: detect parent_valid dtype, normalize, compute 'appears' ----------------
__global__ void prep_kernel(const unsigned char* __restrict__ pv_raw,
                            const int* __restrict__ pidx)
{
    __shared__ int s_hi, s_b0;
    __shared__ int s_app[NINS];
    int tid = threadIdx.x;
    int hi = 0, b0 = 0;
    for (int i = 256 + tid; i < 4096; i += 256) {
        hi |= pv_raw[4*i+1] | pv_raw[4*i+2] | pv_raw[4*i+3];
        b0 |= pv_raw[4*i+0];
    }
    if (tid == 0) { s_hi = 0; s_b0 = 0; }
    __syncthreads();
    if (hi) atomicOr(&s_hi, 1);
    if (b0) atomicOr(&s_b0, 1);
    __syncthreads();
    int mode = (s_hi == 0) ? 0 : (s_b0 == 0 ? 1 : 2);
    for (int i = tid; i < NINS*PAR; i += 256) {
        unsigned char v;
        if (mode == 0)      v = (((const int*)pv_raw)[i]   != 0);
        else if (mode == 1) v = (((const float*)pv_raw)[i] != 0.0f);
        else                v = (pv_raw[i] != 0);
        g_pval[i] = v;
    }
    for (int i = tid; i < NINS; i += 256) s_app[i] = 0;
    __syncthreads();
    for (int i = tid; i < NINS*PAR; i += 256) {
        if (g_pval[i]) atomicAdd(&s_app[pidx[i]], 1);
    }
    __syncthreads();
    for (int i = tid; i < NINS; i += 256) g_appears[i] = s_app[i];
}

__global__ void zero_state_kernel()
{
    int idx = blockIdx.x * blockDim.x + threadIdx.x;
    if (idx < NINS*HID) { g_H[idx] = 0.0f; g_C[idx] = 0.0f; }
}

// permute weight rows: out row n' = in row ((n'%4)*256 + n'/4)
__global__ void permW_kernel(const float* __restrict__ Win, float* __restrict__ Wout)
{
    int np = blockIdx.x;                 // 0..1023 (permuted row)
    int n  = (np & 3) * HID + (np >> 2); // original row
    Wout[(size_t)np * HID + threadIdx.x] = Win[(size_t)n * HID + threadIdx.x];
}

// ============================================================================
// Phase-1: C[M,1024] = A[M,512] @ B[1024,512]^T + (b1+b2), tf32 MMA, split-A
// tile 128x128, BK=32, 8 warps (2x4), warp tile 64x32
// ============================================================================
__device__ __forceinline__ uint32_t cvt_tf32(float v) {
    uint32_t r;
    asm("cvt.rna.tf32.f32 %0, %1;" : "=r"(r) : "f"(v));
    return r;
}
__device__ __forceinline__ void mma_tf32(float* c, uint32_t a0, uint32_t a1,
                                         uint32_t a2, uint32_t a3,
                                         uint32_t b0, uint32_t b1) {
    asm("mma.sync.aligned.m16n8k8.row.col.f32.tf32.tf32.f32 "
        "{%0,%1,%2,%3}, {%4,%5,%6,%7}, {%8,%9}, {%0,%1,%2,%3};"
        : "+f"(c[0]), "+f"(c[1]), "+f"(c[2]), "+f"(c[3])
        : "r"(a0), "r"(a1), "r"(a2), "r"(a3), "r"(b0), "r"(b1));
}

#define T_BM 128
#define T_BN 128
#define T_BK 32
#define T_PAD 36   // row stride in floats (bank-conflict-free, 16B aligned)

__global__ __launch_bounds__(256, 2) void gemm_tf32_kernel(
    const float* __restrict__ A, const float* __restrict__ B,
    float* __restrict__ Cout,
    const float* __restrict__ b1, const float* __restrict__ b2,
    int M, int Kdim)
{
    __shared__ float As[T_BM * T_PAD];
    __shared__ float Bs[T_BN * T_PAD];

    const int bm = blockIdx.y * T_BM;
    const int bn = blockIdx.x * T_BN;
    const int tid  = threadIdx.x;
    const int lane = tid & 31;
    const int warp = tid >> 5;
    const int wm = (warp >> 2) * 64;   // warp row offset in tile
    const int wn = (warp & 3) * 32;    // warp col offset in tile
    const int g   = lane >> 2;         // 0..7
    const int tig = lane & 3;          // 0..3

    float acc[4][4][4];
#pragma unroll
    for (int mi = 0; mi < 4; mi++)
#pragma unroll
        for (int ni = 0; ni < 4; ni++)
#pragma unroll
            for (int r = 0; r < 4; r++) acc[mi][ni][r] = 0.0f;

    for (int kt = 0; kt < Kdim; kt += T_BK) {
        // load A tile (raw fp32) and B tile (tf32-rounded) : 128 rows x 8 float4
#pragma unroll
        for (int u = 0; u < 4; u++) {
            int idx = u * 256 + tid;
            int r   = idx >> 3;
            int c4  = idx & 7;
            float4 av = *(const float4*)(A + (size_t)(bm + r) * Kdim + kt + c4 * 4);
            *(float4*)(As + r * T_PAD + c4 * 4) = av;
            float4 bv = *(const float4*)(B + (size_t)(bn + r) * Kdim + kt + c4 * 4);
            uint4 bq;
            bq.x = cvt_tf32(bv.x); bq.y = cvt_tf32(bv.y);
            bq.z = cvt_tf32(bv.z); bq.w = cvt_tf32(bv.w);
            *(uint4*)(Bs + r * T_PAD + c4 * 4) = bq;
        }
        __syncthreads();

#pragma unroll
        for (int ks = 0; ks < 4; ks++) {
            const int k0 = ks * 8;
            // B fragments
            uint32_t bf[4][2];
#pragma unroll
            for (int ni = 0; ni < 4; ni++) {
                bf[ni][0] = __float_as_uint(Bs[(wn + ni*8 + g) * T_PAD + k0 + tig]);
                bf[ni][1] = __float_as_uint(Bs[(wn + ni*8 + g) * T_PAD + k0 + tig + 4]);
            }
            // A fragments split hi/lo
            uint32_t ahi[4][4], alo[4][4];
#pragma unroll
            for (int mi = 0; mi < 4; mi++) {
                int r0 = (wm + mi*16 + g) * T_PAD + k0;
                int r1 = (wm + mi*16 + 8 + g) * T_PAD + k0;
                float ra0 = As[r0 + tig];
                float ra1 = As[r1 + tig];
                float ra2 = As[r0 + tig + 4];
                float ra3 = As[r1 + tig + 4];
                ahi[mi][0] = cvt_tf32(ra0); alo[mi][0] = __float_as_uint(ra0 - __uint_as_float(ahi[mi][0]));
                ahi[mi][1] = cvt_tf32(ra1); alo[mi][1] = __float_as_uint(ra1 - __uint_as_float(ahi[mi][1]));
                ahi[mi][2] = cvt_tf32(ra2); alo[mi][2] = __float_as_uint(ra2 - __uint_as_float(ahi[mi][2]));
                ahi[mi][3] = cvt_tf32(ra3); alo[mi][3] = __float_as_uint(ra3 - __uint_as_float(ahi[mi][3]));
            }
#pragma unroll
            for (int mi = 0; mi < 4; mi++)
#pragma unroll
                for (int ni = 0; ni < 4; ni++) {
                    mma_tf32(acc[mi][ni], ahi[mi][0], ahi[mi][1], ahi[mi][2], ahi[mi][3],
                             bf[ni][0], bf[ni][1]);
                    mma_tf32(acc[mi][ni], alo[mi][0], alo[mi][1], alo[mi][2], alo[mi][3],
                             bf[ni][0], bf[ni][1]);
                }
        }
        __syncthreads();
    }

    // epilogue: bias + coalesced-ish write (unpermuted columns)
#pragma unroll
    for (int mi = 0; mi < 4; mi++) {
        int r0 = bm + wm + mi*16 + g;
        int r1 = r0 + 8;
#pragma unroll
        for (int ni = 0; ni < 4; ni++) {
            int c = bn + wn + ni*8 + tig*2;
            float bb0 = b1[c] + b2[c];
            float bb1 = b1[c+1] + b2[c+1];
            float2 v0 = make_float2(acc[mi][ni][0] + bb0, acc[mi][ni][1] + bb1);
            float2 v1 = make_float2(acc[mi][ni][2] + bb0, acc[mi][ni][3] + bb1);
            *(float2*)(Cout + (size_t)r0 * G4 + c) = v0;
            *(float2*)(Cout + (size_t)r1 * G4 + c) = v1;
        }
    }
}

// ============================================================================
// Fused fp32 SIMT GEMM (+optional LSTM update epilogue)
// C-tile BM x 64, BK=16, 256 threads (16x16), TM rows per thread
// B must be gate-permuted when FUSE=true (row n' = h*4+gate).
// Add is read with inverse permutation (col = gate*256 + h).
// ============================================================================
template<int BM, int TM, bool FUSE>
__global__ __launch_bounds__(256) void fgemm_kernel(
    const float* __restrict__ A,   // [M, 256]
    const float* __restrict__ B,   // [1024, 256]
    const float* __restrict__ Add, long addStride,
    const float* __restrict__ Cprev,
    float* __restrict__ Hout, float* __restrict__ Cstate,
    const float* __restrict__ b1, const float* __restrict__ b2)
{
    const int K = HID; // 256
    __shared__ float As[16][BM];
    __shared__ float Bs[16][64];

    const int bm = blockIdx.y * BM;
    const int bn = blockIdx.x * 64;
    const int tid = threadIdx.x;
    const int tx = tid & 15, ty = tid >> 4;

    float acc[TM][4];
#pragma unroll
    for (int i = 0; i < TM; i++)
#pragma unroll
        for (int j = 0; j < 4; j++) acc[i][j] = 0.0f;

    for (int kt = 0; kt < K; kt += 16) {
        // A tile: BM*16 floats = BM*4 float4
        for (int idx = tid; idx < BM * 4; idx += 256) {
            int r = idx >> 2, c4 = idx & 3;
            float4 v = *(const float4*)(A + (size_t)(bm + r) * K + kt + c4 * 4);
            As[c4*4+0][r] = v.x; As[c4*4+1][r] = v.y;
            As[c4*4+2][r] = v.z; As[c4*4+3][r] = v.w;
        }
        // B tile: 64*16 = 256 float4
        {
            int r = tid >> 2, c4 = tid & 3;
            float4 v = *(const float4*)(B + (size_t)(bn + r) * K + kt + c4 * 4);
            Bs[c4*4+0][r] = v.x; Bs[c4*4+1][r] = v.y;
            Bs[c4*4+2][r] = v.z; Bs[c4*4+3][r] = v.w;
        }
        __syncthreads();
#pragma unroll
        for (int kk = 0; kk < 16; kk++) {
            float b0 = Bs[kk][tx*4+0], bb1 = Bs[kk][tx*4+1];
            float b2v = Bs[kk][tx*4+2], b3 = Bs[kk][tx*4+3];
#pragma unroll
            for (int i = 0; i < TM; i++) {
                float a = As[kk][ty*TM + i];
                acc[i][0] += a * b0; acc[i][1] += a * bb1;
                acc[i][2] += a * b2v; acc[i][3] += a * b3;
            }
        }
        __syncthreads();
    }

    if (FUSE) {
        int h = (bn >> 2) + tx;   // hidden index for this thread's quad
#pragma unroll
        for (int i = 0; i < TM; i++) {
            int m = bm + ty*TM + i;
            const float* ad = Add + (size_t)m * addStride;
            float gi = acc[i][0] + ad[0*HID + h];
            float gf = acc[i][1] + ad[1*HID + h];
            float gg = acc[i][2] + ad[2*HID + h];
            float go = acc[i][3] + ad[3*HID + h];
            float c  = Cprev[(size_t)m * HID + h];
            float si = 1.0f / (1.0f + expf(-gi));
            float sf = 1.0f / (1.0f + expf(-gf));
            float so = 1.0f / (1.0f + expf(-go));
            float cn = sf * c + si * tanhf(gg);
            float hn = so * tanhf(cn);
            Cstate[(size_t)m * HID + h] = cn;
            Hout[(size_t)m * HID + h]   = hn;
        }
    } else {
#pragma unroll
        for (int i = 0; i < TM; i++) {
            int m = bm + ty*TM + i;
#pragma unroll
            for (int j = 0; j < 4; j++) {
                int n = bn + tx*4 + j;
                Hout[(size_t)m * G4 + n] = acc[i][j] + b1[n] + b2[n];
            }
        }
    }
}

// ---------------- per-level parent gather (max combine) ----------------
__global__ void gather_kernel(const int* __restrict__ pidx, int l)
{
    int r   = blockIdx.x;
    int row = l * KROWS + r;
    int h   = threadIdx.x;
    __shared__ int sp[PAR];
    __shared__ int sv[PAR];
    if (h < PAR) {
        sp[h] = pidx[row*PAR + h];
        sv[h] = g_pval[row*PAR + h];
    }
    __syncthreads();
    float mh = -1e30f, mc = -1e30f;
    int has = 0;
#pragma unroll
    for (int p = 0; p < PAR; p++) {
        if (sv[p]) {
            has = 1;
            mh = fmaxf(mh, g_Hi[(size_t)sp[p]*HID + h]);
            mc = fmaxf(mc, g_Ci[(size_t)sp[p]*HID + h]);
        }
    }
    g_h0[r*HID + h] = has ? mh : 0.0f;
    g_c0[r*HID + h] = has ? mc : 0.0f;
}

// ---------------- final: masked max over roots, then dot with Wlin ----------------
__global__ void final1_kernel()
{
    int b = blockIdx.x;
    int h = threadIdx.x;
    float m = -1e30f;
    for (int r = b*32; r < b*32 + 32; r++)
        if (g_appears[r] == 0) m = fmaxf(m, g_Hi[(size_t)r*HID + h]);
    g_partial[b*HID + h] = m;
}

__global__ void final2_kernel(const float* __restrict__ Wlin,
                              const float* __restrict__ blin,
                              float* __restrict__ out)
{
    int h = threadIdx.x;
    float m = -1e30f;
    for (int b = 0; b < 64; b++) m = fmaxf(m, g_partial[b*HID + h]);
    float v = m * Wlin[h];
    __shared__ float s[256];
    s[h] = v;
    __syncthreads();
    for (int st = 128; st > 0; st >>= 1) {
        if (h < st) s[h] += s[h + st];
        __syncthreads();
    }
    if (h == 0) out[0] = s[0] + blin[0];
}

// ---------------- launch ----------------
extern "C" void kernel_launch(void* const* d_in, const int* in_sizes, int n_in,
                              void* d_out, int out_size)
{
    const float* tokens   = (const float*)d_in[0];
    const int*   pidx     = (const int*)  d_in[1];
    const unsigned char* pval = (const unsigned char*)d_in[2];
    const float* Wih_tok  = (const float*)d_in[3];
    const float* Whh_tok  = (const float*)d_in[4];
    const float* bih_tok  = (const float*)d_in[5];
    const float* bhh_tok  = (const float*)d_in[6];
    const float* Wih_ins  = (const float*)d_in[7];
    const float* Whh_ins  = (const float*)d_in[8];
    const float* bih_ins  = (const float*)d_in[9];
    const float* bhh_ins  = (const float*)d_in[10];
    const float* Wlin     = (const float*)d_in[11];
    const float* blin     = (const float*)d_in[12];
    float* out = (float*)d_out;

    float *pXp, *pH, *pC, *pH2, *pC2, *pGx, *pHi, *pCi, *ph0, *pc0, *pWtP, *pWiP;
    cudaGetSymbolAddress((void**)&pXp,  g_Xp);
    cudaGetSymbolAddress((void**)&pH,   g_H);
    cudaGetSymbolAddress((void**)&pC,   g_C);
    cudaGetSymbolAddress((void**)&pH2,  g_H2);
    cudaGetSymbolAddress((void**)&pC2,  g_C2);
    cudaGetSymbolAddress((void**)&pGx,  g_Gx);
    cudaGetSymbolAddress((void**)&pHi,  g_Hi);
    cudaGetSymbolAddress((void**)&pCi,  g_Ci);
    cudaGetSymbolAddress((void**)&ph0,  g_h0);
    cudaGetSymbolAddress((void**)&pc0,  g_c0);
    cudaGetSymbolAddress((void**)&pWtP, g_WhhTokP);
    cudaGetSymbolAddress((void**)&pWiP, g_WhhInsP);

    prep_kernel<<<1, 256>>>(pval, pidx);
    permW_kernel<<<G4, HID>>>(Whh_tok, pWtP);
    permW_kernel<<<G4, HID>>>(Whh_ins, pWiP);
    zero_state_kernel<<<(NINS*HID + 255)/256, 256>>>();

    // Phase 1: Xp = tokens @ Wih_tok^T + (bih+bhh)   [32768 x 1024, K=512]  (tf32 split-A)
    gemm_tf32_kernel<<<dim3(G4/T_BN, (NINS*TOK)/T_BM), 256>>>(
        tokens, Wih_tok, pXp, bih_tok, bhh_tok, NINS*TOK, EMB);

    // Phase 2: token-LSTM recurrence, fused GEMM+update, ping-pong state
    for (int t = 0; t < TOK; t++) {
        const float* Hin = (t & 1) ? pH2 : pH;
        const float* Cin = (t & 1) ? pC2 : pC;
        float* Ho = (t & 1) ? pH : pH2;
        float* Co = (t & 1) ? pC : pC2;
        fgemm_kernel<128, 8, true><<<dim3(16, NINS/128), 256>>>(
            Hin, pWtP, pXp + (size_t)t * G4, (long)TOK * G4,
            Cin, Ho, Co, nullptr, nullptr);
    }
    // after 16 steps final hidden is in g_H
    // Phase 3a: Gx = ins_embed @ Wih_ins^T + biases (unpermuted output)
    fgemm_kernel<128, 8, false><<<dim3(16, NINS/128), 256>>>(
        pH, Wih_ins, nullptr, 0, nullptr, pGx, nullptr, bih_ins, bhh_ins);

    // Phase 3b: DAG levels, fused
    for (int l = 0; l < LEVELS; l++) {
        gather_kernel<<<KROWS, HID>>>(pidx, l);
        fgemm_kernel<32, 2, true><<<dim3(16, KROWS/32), 256>>>(
            ph0, pWiP, pGx + (size_t)l * KROWS * G4, (long)G4,
            pc0, pHi + (size_t)l * KROWS * HID, pCi + (size_t)l * KROWS * HID,
            nullptr, nullptr);
    }

    final1_kernel<<<64, 256>>>();
    final2_kernel<<<1, 256>>>(Wlin, blin, out);
}

// round 4
// speedup vs baseline: 2.1486x; 1.0593x over previous
#include <cuda_runtime.h>
#include <math.h>
#include <stdint.h>

#define NINS   2048
#define TOK    16
#define EMB    512
#define HID    256
#define G4     (4*HID)      // 1024
#define PAR    8
#define LEVELS 16
#define KROWS  (NINS/LEVELS) // 128

// ---------------- scratch (static device globals; no allocation) ----------------
__device__ float g_Xp[NINS*TOK*G4];      // 128 MiB: token input projections (unpermuted cols)
__device__ float g_H[NINS*HID];
__device__ float g_C[NINS*HID];
__device__ float g_H2[NINS*HID];
__device__ float g_C2[NINS*HID];
__device__ float g_Gx[NINS*G4];
__device__ float g_Hi[NINS*HID];
__device__ float g_Ci[NINS*HID];
__device__ float g_h0[KROWS*HID];
__device__ float g_c0[KROWS*HID];
__device__ float g_WhhTokP[G4*HID];      // gate-interleaved permuted Whh_tok (row n' = h*4+gate)
__device__ float g_WhhInsP[G4*HID];
__device__ unsigned char g_pval[NINS*PAR];
__device__ int   g_appears[NINS];
__device__ float g_partial[64*HID];

// ---------------- prep ----------------
__global__ void prep_kernel(const unsigned char* __restrict__ pv_raw,
                            const int* __restrict__ pidx)
{
    __shared__ int s_hi, s_b0;
    __shared__ int s_app[NINS];
    int tid = threadIdx.x;
    int hi = 0, b0 = 0;
    for (int i = 256 + tid; i < 4096; i += 256) {
        hi |= pv_raw[4*i+1] | pv_raw[4*i+2] | pv_raw[4*i+3];
        b0 |= pv_raw[4*i+0];
    }
    if (tid == 0) { s_hi = 0; s_b0 = 0; }
    __syncthreads();
    if (hi) atomicOr(&s_hi, 1);
    if (b0) atomicOr(&s_b0, 1);
    __syncthreads();
    int mode = (s_hi == 0) ? 0 : (s_b0 == 0 ? 1 : 2);
    for (int i = tid; i < NINS*PAR; i += 256) {
        unsigned char v;
        if (mode == 0)      v = (((const int*)pv_raw)[i]   != 0);
        else if (mode == 1) v = (((const float*)pv_raw)[i] != 0.0f);
        else                v = (pv_raw[i] != 0);
        g_pval[i] = v;
    }
    for (int i = tid; i < NINS; i += 256) s_app[i] = 0;
    __syncthreads();
    for (int i = tid; i < NINS*PAR; i += 256) {
        if (g_pval[i]) atomicAdd(&s_app[pidx[i]], 1);
    }
    __syncthreads();
    for (int i = tid; i < NINS; i += 256) g_appears[i] = s_app[i];
}

// permute weight rows: out row n' = in row ((n'%4)*256 + n'/4)
__global__ void permW_kernel(const float* __restrict__ Win, float* __restrict__ Wout)
{
    int np = blockIdx.x;
    int n  = (np & 3) * HID + (np >> 2);
    Wout[(size_t)np * HID + threadIdx.x] = Win[(size_t)n * HID + threadIdx.x];
}

// ---------------- tf32 helpers ----------------
__device__ __forceinline__ uint32_t cvt_tf32(float v) {
    uint32_t r;
    asm("cvt.rna.tf32.f32 %0, %1;" : "=r"(r) : "f"(v));
    return r;
}
__device__ __forceinline__ void mma_tf32(float* c, uint32_t a0, uint32_t a1,
                                         uint32_t a2, uint32_t a3,
                                         uint32_t b0, uint32_t b1) {
    asm("mma.sync.aligned.m16n8k8.row.col.f32.tf32.tf32.f32 "
        "{%0,%1,%2,%3}, {%4,%5,%6,%7}, {%8,%9}, {%0,%1,%2,%3};"
        : "+f"(c[0]), "+f"(c[1]), "+f"(c[2]), "+f"(c[3])
        : "r"(a0), "r"(a1), "r"(a2), "r"(a3), "r"(b0), "r"(b1));
}
__device__ __forceinline__ void cp_async16(void* smem, const void* gmem) {
    uint32_t s = (uint32_t)__cvta_generic_to_shared(smem);
    asm volatile("cp.async.cg.shared.global [%0], [%1], 16;\n" :: "r"(s), "l"(gmem));
}

// ============================================================================
// Unified tf32 split-A MMA kernel. C[M,1024] = A[M,K] @ B[1024,K]^T (2-pass A).
// Tile 128x128, BK=16, 2-stage cp.async pipeline, 8 warps (2x4).
// FUSE: B is gate-interleaved; epilogue does the LSTM update via shfl exchange.
//   gates = acc + Add[row][gate*256+h];  c = Cprev (or 0);  write Hout/Cstate [row*256+h]
//   A==nullptr -> acc=0 (t=0 step).
// !FUSE: Cout[row*1024+col] = acc + b1[col] + b2[col]
// ============================================================================
#define T_PAD 20

template<int KDIM, bool FUSE>
__global__ __launch_bounds__(256, 2) void mma_kernel(
    const float* __restrict__ A, const float* __restrict__ B,
    float* __restrict__ Hout, float* __restrict__ Cstate,
    const float* __restrict__ Add, long addStride,
    const float* __restrict__ Cprev,
    const float* __restrict__ b1, const float* __restrict__ b2)
{
    __shared__ float As[2*128*T_PAD];
    __shared__ float Bs[2*128*T_PAD];

    const int bm = blockIdx.y * 128;
    const int bn = blockIdx.x * 128;
    const int tid  = threadIdx.x;
    const int lane = tid & 31;
    const int warp = tid >> 5;
    const int wm = (warp >> 2) * 64;
    const int wn = (warp & 3) * 32;
    const int g   = lane >> 2;
    const int tig = lane & 3;

    float acc[4][4][4];
#pragma unroll
    for (int mi = 0; mi < 4; mi++)
#pragma unroll
        for (int ni = 0; ni < 4; ni++)
#pragma unroll
            for (int r = 0; r < 4; r++) acc[mi][ni][r] = 0.0f;

    if (A != nullptr) {
        const int NT = KDIM / 16;
        // prefetch stage 0
        {
#pragma unroll
            for (int u = 0; u < 2; u++) {
                int idx = u * 256 + tid;
                int r = idx >> 2, c4 = idx & 3;
                cp_async16(As + r * T_PAD + c4 * 4, A + (size_t)(bm + r) * KDIM + c4 * 4);
                cp_async16(Bs + r * T_PAD + c4 * 4, B + (size_t)(bn + r) * KDIM + c4 * 4);
            }
            asm volatile("cp.async.commit_group;\n");
        }
        for (int kt = 0; kt < NT; kt++) {
            int cur = kt & 1;
            if (kt + 1 < NT) {
                int nxt = (kt + 1) & 1;
                const float* Ap = A + (size_t)bm * KDIM + (kt + 1) * 16;
                const float* Bp = B + (size_t)bn * KDIM + (kt + 1) * 16;
#pragma unroll
                for (int u = 0; u < 2; u++) {
                    int idx = u * 256 + tid;
                    int r = idx >> 2, c4 = idx & 3;
                    cp_async16(As + nxt * 128 * T_PAD + r * T_PAD + c4 * 4,
                               Ap + (size_t)r * KDIM + c4 * 4);
                    cp_async16(Bs + nxt * 128 * T_PAD + r * T_PAD + c4 * 4,
                               Bp + (size_t)r * KDIM + c4 * 4);
                }
                asm volatile("cp.async.commit_group;\n");
                asm volatile("cp.async.wait_group 1;\n");
            } else {
                asm volatile("cp.async.wait_group 0;\n");
            }
            __syncthreads();

            const float* Asb = As + cur * 128 * T_PAD;
            const float* Bsb = Bs + cur * 128 * T_PAD;
#pragma unroll
            for (int ks = 0; ks < 2; ks++) {
                const int k0 = ks * 8;
                uint32_t bf[4][2];
#pragma unroll
                for (int ni = 0; ni < 4; ni++) {
                    bf[ni][0] = cvt_tf32(Bsb[(wn + ni*8 + g) * T_PAD + k0 + tig]);
                    bf[ni][1] = cvt_tf32(Bsb[(wn + ni*8 + g) * T_PAD + k0 + tig + 4]);
                }
                uint32_t ahi[4][4], alo[4][4];
#pragma unroll
                for (int mi = 0; mi < 4; mi++) {
                    int r0 = (wm + mi*16 + g) * T_PAD + k0;
                    int r1 = (wm + mi*16 + 8 + g) * T_PAD + k0;
                    float ra0 = Asb[r0 + tig];
                    float ra1 = Asb[r1 + tig];
                    float ra2 = Asb[r0 + tig + 4];
                    float ra3 = Asb[r1 + tig + 4];
                    ahi[mi][0] = cvt_tf32(ra0); alo[mi][0] = __float_as_uint(ra0 - __uint_as_float(ahi[mi][0]));
                    ahi[mi][1] = cvt_tf32(ra1); alo[mi][1] = __float_as_uint(ra1 - __uint_as_float(ahi[mi][1]));
                    ahi[mi][2] = cvt_tf32(ra2); alo[mi][2] = __float_as_uint(ra2 - __uint_as_float(ahi[mi][2]));
                    ahi[mi][3] = cvt_tf32(ra3); alo[mi][3] = __float_as_uint(ra3 - __uint_as_float(ahi[mi][3]));
                }
#pragma unroll
                for (int mi = 0; mi < 4; mi++)
#pragma unroll
                    for (int ni = 0; ni < 4; ni++) {
                        mma_tf32(acc[mi][ni], ahi[mi][0], ahi[mi][1], ahi[mi][2], ahi[mi][3],
                                 bf[ni][0], bf[ni][1]);
                        mma_tf32(acc[mi][ni], alo[mi][0], alo[mi][1], alo[mi][2], alo[mi][3],
                                 bf[ni][0], bf[ni][1]);
                    }
            }
            __syncthreads();
        }
    }

    if (FUSE) {
        // gate-interleaved columns: col = h*4 + gate.  Each thread's fragment has
        // 2 adjacent cols (rows g and g+8).  shfl_xor(1) completes the quad.
#pragma unroll
        for (int mi = 0; mi < 4; mi++) {
#pragma unroll
            for (int ni = 0; ni < 4; ni++) {
                float c0 = acc[mi][ni][0], c1 = acc[mi][ni][1];
                float c2 = acc[mi][ni][2], c3 = acc[mi][ni][3];
                float x0 = __shfl_xor_sync(0xffffffffu, c0, 1);
                float x1 = __shfl_xor_sync(0xffffffffu, c1, 1);
                float x2 = __shfl_xor_sync(0xffffffffu, c2, 1);
                float x3 = __shfl_xor_sync(0xffffffffu, c3, 1);
                int q = tig >> 1;
                int h = (bn + wn + ni*8 + q*4) >> 2;
                int row;
                float gi, gf, gg, go;
                if ((tig & 1) == 0) {
                    row = bm + wm + mi*16 + g;
                    gi = c0; gf = c1; gg = x0; go = x1;
                } else {
                    row = bm + wm + mi*16 + 8 + g;
                    gi = x2; gf = x3; gg = c2; go = c3;
                }
                const float* ad = Add + (size_t)row * addStride;
                gi += ad[h];
                gf += ad[HID + h];
                gg += ad[2*HID + h];
                go += ad[3*HID + h];
                float c = Cprev ? Cprev[(size_t)row * HID + h] : 0.0f;
                float si = 1.0f / (1.0f + expf(-gi));
                float sf = 1.0f / (1.0f + expf(-gf));
                float so = 1.0f / (1.0f + expf(-go));
                float cn = sf * c + si * tanhf(gg);
                float hn = so * tanhf(cn);
                Cstate[(size_t)row * HID + h] = cn;
                Hout[(size_t)row * HID + h]   = hn;
            }
        }
    } else {
#pragma unroll
        for (int mi = 0; mi < 4; mi++) {
            int r0 = bm + wm + mi*16 + g;
            int r1 = r0 + 8;
#pragma unroll
            for (int ni = 0; ni < 4; ni++) {
                int c = bn + wn + ni*8 + tig*2;
                float bb0 = b1[c] + b2[c];
                float bb1 = b1[c+1] + b2[c+1];
                float2 v0 = make_float2(acc[mi][ni][0] + bb0, acc[mi][ni][1] + bb1);
                float2 v1 = make_float2(acc[mi][ni][2] + bb0, acc[mi][ni][3] + bb1);
                *(float2*)(Hout + (size_t)r0 * G4 + c) = v0;
                *(float2*)(Hout + (size_t)r1 * G4 + c) = v1;
            }
        }
    }
}

// ---------------- per-level parent gather (max combine) ----------------
__global__ void gather_kernel(const int* __restrict__ pidx, int l)
{
    int r   = blockIdx.x;
    int row = l * KROWS + r;
    int h   = threadIdx.x;
    __shared__ int sp[PAR];
    __shared__ int sv[PAR];
    if (h < PAR) {
        sp[h] = pidx[row*PAR + h];
        sv[h] = g_pval[row*PAR + h];
    }
    __syncthreads();
    float mh = -1e30f, mc = -1e30f;
    int has = 0;
#pragma unroll
    for (int p = 0; p < PAR; p++) {
        if (sv[p]) {
            has = 1;
            mh = fmaxf(mh, g_Hi[(size_t)sp[p]*HID + h]);
            mc = fmaxf(mc, g_Ci[(size_t)sp[p]*HID + h]);
        }
    }
    g_h0[r*HID + h] = has ? mh : 0.0f;
    g_c0[r*HID + h] = has ? mc : 0.0f;
}

// ---------------- final: masked max over roots, then dot with Wlin ----------------
__global__ void final1_kernel()
{
    int b = blockIdx.x;
    int h = threadIdx.x;
    float m = -1e30f;
    for (int r = b*32; r < b*32 + 32; r++)
        if (g_appears[r] == 0) m = fmaxf(m, g_Hi[(size_t)r*HID + h]);
    g_partial[b*HID + h] = m;
}

__global__ void final2_kernel(const float* __restrict__ Wlin,
                              const float* __restrict__ blin,
                              float* __restrict__ out)
{
    int h = threadIdx.x;
    float m = -1e30f;
    for (int b = 0; b < 64; b++) m = fmaxf(m, g_partial[b*HID + h]);
    float v = m * Wlin[h];
    __shared__ float s[256];
    s[h] = v;
    __syncthreads();
    for (int st = 128; st > 0; st >>= 1) {
        if (h < st) s[h] += s[h + st];
        __syncthreads();
    }
    if (h == 0) out[0] = s[0] + blin[0];
}

// ---------------- launch ----------------
extern "C" void kernel_launch(void* const* d_in, const int* in_sizes, int n_in,
                              void* d_out, int out_size)
{
    const float* tokens   = (const float*)d_in[0];
    const int*   pidx     = (const int*)  d_in[1];
    const unsigned char* pval = (const unsigned char*)d_in[2];
    const float* Wih_tok  = (const float*)d_in[3];
    const float* Whh_tok  = (const float*)d_in[4];
    const float* bih_tok  = (const float*)d_in[5];
    const float* bhh_tok  = (const float*)d_in[6];
    const float* Wih_ins  = (const float*)d_in[7];
    const float* Whh_ins  = (const float*)d_in[8];
    const float* bih_ins  = (const float*)d_in[9];
    const float* bhh_ins  = (const float*)d_in[10];
    const float* Wlin     = (const float*)d_in[11];
    const float* blin     = (const float*)d_in[12];
    float* out = (float*)d_out;

    float *pXp, *pH, *pC, *pH2, *pC2, *pGx, *pHi, *pCi, *ph0, *pc0, *pWtP, *pWiP;
    cudaGetSymbolAddress((void**)&pXp,  g_Xp);
    cudaGetSymbolAddress((void**)&pH,   g_H);
    cudaGetSymbolAddress((void**)&pC,   g_C);
    cudaGetSymbolAddress((void**)&pH2,  g_H2);
    cudaGetSymbolAddress((void**)&pC2,  g_C2);
    cudaGetSymbolAddress((void**)&pGx,  g_Gx);
    cudaGetSymbolAddress((void**)&pHi,  g_Hi);
    cudaGetSymbolAddress((void**)&pCi,  g_Ci);
    cudaGetSymbolAddress((void**)&ph0,  g_h0);
    cudaGetSymbolAddress((void**)&pc0,  g_c0);
    cudaGetSymbolAddress((void**)&pWtP, g_WhhTokP);
    cudaGetSymbolAddress((void**)&pWiP, g_WhhInsP);

    prep_kernel<<<1, 256>>>(pval, pidx);
    permW_kernel<<<G4, HID>>>(Whh_tok, pWtP);
    permW_kernel<<<G4, HID>>>(Whh_ins, pWiP);

    // Phase 1: Xp = tokens @ Wih_tok^T + (bih+bhh)   [32768 x 1024, K=512]
    mma_kernel<EMB, false><<<dim3(8, 256), 256>>>(
        tokens, Wih_tok, pXp, nullptr, nullptr, 0, nullptr, bih_tok, bhh_tok);

    // Phase 2: token-LSTM recurrence, fused.  t=0: H=C=0 -> skip GEMM (A=null).
    for (int t = 0; t < TOK; t++) {
        const float* Hin = (t == 0) ? nullptr : ((t & 1) ? pH2 : pH);
        const float* Cin = (t == 0) ? nullptr : ((t & 1) ? pC2 : pC);
        float* Ho = (t & 1) ? pH : pH2;
        float* Co = (t & 1) ? pC : pC2;
        mma_kernel<HID, true><<<dim3(8, 16), 256>>>(
            Hin, pWtP, Ho, Co, pXp + (size_t)t * G4, (long)TOK * G4,
            Cin, nullptr, nullptr);
    }
    // after 16 steps final hidden is in g_H
    // Phase 3a: Gx = ins_embed @ Wih_ins^T + biases (unpermuted output)
    mma_kernel<HID, false><<<dim3(8, 16), 256>>>(
        pH, Wih_ins, pGx, nullptr, nullptr, 0, nullptr, bih_ins, bhh_ins);

    // Phase 3b: DAG levels, fused tf32
    for (int l = 0; l < LEVELS; l++) {
        gather_kernel<<<KROWS, HID>>>(pidx, l);
        mma_kernel<HID, true><<<dim3(8, 1), 256>>>(
            ph0, pWiP, pHi + (size_t)l * KROWS * HID, pCi + (size_t)l * KROWS * HID,
            pGx + (size_t)l * KROWS * G4, (long)G4, pc0, nullptr, nullptr);
    }

    final1_kernel<<<64, 256>>>();
    final2_kernel<<<1, 256>>>(Wlin, blin, out);
}